// round 15
// baseline (speedup 1.0000x reference)
#include <cuda_runtime.h>
#include <cstdint>
#include <math.h>

#define HH 128
#define WW 128
#define HWp 16384
#define Cin 64
#define Cout 64
#define Bsz 2
#define NPIX 32768

// ---------------------------------------------------------------------------
// Scratch (no allocations allowed)
// ---------------------------------------------------------------------------
__device__ float  g_om[Bsz*27*HWp];     // 18 raw offsets + 9 sigmoided masks
__device__ float4 g_wB4[9*8*4*32];      // kB B-frags nt-pair packed
__device__ float4 g_wA4[9*8*2*32];      // kA B-frags nt-pair packed
__device__ float  g_tmp[Bsz*Cout*HWp];  // pre-BN conv output (NCHW)
__device__ float  g_part[512*2];        // kC partial sums [c*8+slab][{s,q}]

// ---------------------------------------------------------------------------
__device__ __forceinline__ uint32_t cvt_tf32(float v) {
    uint32_t r;
    asm("cvt.rna.tf32.f32 %0, %1;" : "=r"(r) : "f"(v));
    return r;
}
__device__ __forceinline__ void mma_t(float* d,
    uint32_t a0, uint32_t a1, uint32_t a2, uint32_t a3,
    uint32_t b0, uint32_t b1)
{
    asm volatile("mma.sync.aligned.m16n8k8.row.col.f32.tf32.tf32.f32 "
        "{%0,%1,%2,%3}, {%4,%5,%6,%7}, {%8,%9}, {%0,%1,%2,%3};"
        : "+f"(d[0]), "+f"(d[1]), "+f"(d[2]), "+f"(d[3])
        : "r"(a0), "r"(a1), "r"(a2), "r"(a3), "r"(b0), "r"(b1));
}

// ---------------------------------------------------------------------------
// kW: pack both weight sets (merged kWB + kWA). Weights keep RNA rounding.
// ---------------------------------------------------------------------------
__global__ void kW(const float* __restrict__ w,
                   const float* __restrict__ off_w, const float* __restrict__ mask_w)
{
    if (blockIdx.x < 36) {
        int i = blockIdx.x * 256 + threadIdx.x;        // 9*8*4*32 = 9216
        if (i >= 9*8*4*32) return;
        int lane = i & 31;
        int ntp  = (i >> 5) & 3;
        int ks   = (i >> 7) & 7;
        int tap  = i >> 10;
        int o0 = (ntp * 2) * 8 + (lane >> 2);
        int o1 = o0 + 8;
        int c0 = ks * 8 + (lane & 3);
        float4 r;
        r.x = __uint_as_float(cvt_tf32(w[o0 * 576 + c0 * 9 + tap]));
        r.y = __uint_as_float(cvt_tf32(w[o0 * 576 + (c0 + 4) * 9 + tap]));
        r.z = __uint_as_float(cvt_tf32(w[o1 * 576 + c0 * 9 + tap]));
        r.w = __uint_as_float(cvt_tf32(w[o1 * 576 + (c0 + 4) * 9 + tap]));
        g_wB4[i] = r;
    } else {
        int i = (blockIdx.x - 36) * 256 + threadIdx.x; // 9*8*2*32 = 4608
        if (i >= 9*8*2*32) return;
        int lane = i & 31;
        int ntp  = (i >> 5) & 1;
        int ks   = (i >> 6) & 7;
        int tap  = i >> 9;
        int c0 = ks * 8 + (lane & 3);
        float v[4];
#pragma unroll
        for (int h = 0; h < 2; h++) {
            int o = (ntp * 2 + h) * 8 + (lane >> 2);
            float a = 0.f, bb = 0.f;
            if (o < 18) {
                a  = off_w[o * 576 + c0 * 9 + tap];
                bb = off_w[o * 576 + (c0 + 4) * 9 + tap];
            } else if (o < 27) {
                a  = mask_w[(o - 18) * 576 + c0 * 9 + tap];
                bb = mask_w[(o - 18) * 576 + (c0 + 4) * 9 + tap];
            }
            v[h * 2]     = __uint_as_float(cvt_tf32(a));
            v[h * 2 + 1] = __uint_as_float(cvt_tf32(bb));
        }
        g_wA4[i] = make_float4(v[0], v[1], v[2], v[3]);
    }
}

// ---------------------------------------------------------------------------
// kA6: offset/mask conv, smem-tiled, K-split x4 (R11; A-cvt removed —
// mma.tf32 reads tf32 bits of raw fp32 = round-toward-zero).
// ---------------------------------------------------------------------------
#define TPA 72

__global__ __launch_bounds__(128, 8) void kA6(
    const float* __restrict__ x,
    const float* __restrict__ off_b, const float* __restrict__ mask_b)
{
    __shared__ float ts[54 * TPA];

    int tid = threadIdx.x, kh = tid >> 5, lane = tid & 31;
    int sidx = blockIdx.x;
    int b = sidx >> 10;
    int y = (sidx >> 3) & 127;
    int p0c = (sidx & 7) * 16;
    int p0 = p0c + (lane >> 2);
    int p1 = p0 + 8;
    const float* xb = x + b * Cin * HWp;

    for (int i = tid; i < 32 * 54; i += 128) {
        int pr = i / 54;
        int rr = i - pr * 54;
        int r = rr / 18, col = rr - r * 18;
        int gy = y - 1 + r, gx = p0c - 1 + col;
        bool v = ((unsigned)gy < HH && (unsigned)gx < WW);
        int c_lo = ((pr >> 2) << 3) + (pr & 3);
        const float* src = xb + c_lo * HWp + gy * WW + gx;
        float a  = v ? src[0]       : 0.f;
        float bb = v ? src[4 * HWp] : 0.f;
        int cw = ((pr >> 2) << 3) + ((pr & 3) << 1);
        *(float2*)(ts + rr * TPA + cw) = make_float2(a, bb);
    }
    __syncthreads();

    float acc[4][4];
#pragma unroll
    for (int n = 0; n < 4; n++)
#pragma unroll
        for (int j = 0; j < 4; j++) acc[n][j] = 0.f;

    int cwb = (kh << 4) + ((lane & 3) << 1);

#pragma unroll
    for (int tap = 0; tap < 9; tap++) {
        int posA = (tap / 3) * 18 + (tap % 3) + (lane >> 2);
        int posB = posA + 8;
#pragma unroll
        for (int kq = 0; kq < 2; kq++) {
            int cw = cwb + (kq << 3);
            float2 A  = *(const float2*)(ts + posA * TPA + cw);
            float2 Bv = *(const float2*)(ts + posB * TPA + cw);
            uint32_t a0 = __float_as_uint(A.x);
            uint32_t a1 = __float_as_uint(Bv.x);
            uint32_t a2 = __float_as_uint(A.y);
            uint32_t a3 = __float_as_uint(Bv.y);
            const float4* bq = g_wA4 + ((tap * 8 + kh * 2 + kq) * 2) * 32 + lane;
#pragma unroll
            for (int ntp = 0; ntp < 2; ntp++) {
                float4 bv = __ldg(bq + ntp * 32);
                mma_t(acc[ntp * 2],     a0, a1, a2, a3,
                      __float_as_uint(bv.x), __float_as_uint(bv.y));
                mma_t(acc[ntp * 2 + 1], a0, a1, a2, a3,
                      __float_as_uint(bv.z), __float_as_uint(bv.w));
            }
        }
    }

    __syncthreads();
    float* red = ts;
    if (kh != 0) {
#pragma unroll
        for (int n = 0; n < 4; n++)
#pragma unroll
            for (int j = 0; j < 4; j++)
                red[(kh - 1) * 512 + (n * 4 + j) * 32 + lane] = acc[n][j];
    }
    __syncthreads();
    if (kh == 0) {
        float* omb = g_om + b * 27 * HWp;
        int yx0 = y * WW + p0, yx1 = y * WW + p1;
#pragma unroll
        for (int nt = 0; nt < 4; nt++) {
            int o = nt * 8 + (lane & 3) * 2;
#pragma unroll
            for (int j = 0; j < 2; j++) {
                int oc = o + j;
                if (oc < 27) {
                    float bias = (oc < 18) ? off_b[oc] : mask_b[oc - 18];
                    float r0 = acc[nt][j]     + bias;
                    float r1 = acc[nt][j + 2] + bias;
#pragma unroll
                    for (int w = 0; w < 3; w++) {
                        r0 += red[w * 512 + (nt * 4 + j) * 32 + lane];
                        r1 += red[w * 512 + (nt * 4 + j + 2) * 32 + lane];
                    }
                    if (oc >= 18) {
                        r0 = 1.f / (1.f + expf(-r0));
                        r1 = 1.f / (1.f + expf(-r1));
                    }
                    omb[oc * HWp + yx0] = r0;
                    omb[oc * HWp + yx1] = r1;
                }
            }
        }
    }
}

// ---------------------------------------------------------------------------
// kB15: R11 mainloop, A-cvt removed (raw fp32 bits into mma.tf32).
// Everything else identical to the 74.5us kB11.
// ---------------------------------------------------------------------------
#define TP 72

__global__ __launch_bounds__(128, 7) void kB15(const float* __restrict__ x)
{
    __shared__ float  ts[100 * TP];     // tile; reused as reduction buffer
    __shared__ float4 sw[9][16];
    __shared__ int    sp[9][16];
    __shared__ int    allin[9];

    int tid = threadIdx.x, kh = tid >> 5, lane = tid & 31;
    int sidx = blockIdx.x;
    int b = sidx >> 10;
    int y = (sidx >> 3) & 127;
    int p0c = (sidx & 7) * 16;
    int p0 = p0c + (lane >> 2);
    int p1 = p0 + 8;
    const float* xb  = x + b * Cin * HWp;
    const float* omb = g_om + b * 27 * HWp;
    int yx0 = y * WW + p0, yx1 = y * WW + p1;

    if (tid < 9) allin[tid] = 1;
    __syncthreads();

    // ---- fill tile: rows y-2..y+2, cols p0c-2..p0c+17, channel-pair STS.64 ----
    for (int i = tid; i < 32 * 100; i += 128) {
        int pr = i / 100;
        int rr = i - pr * 100;
        int r = rr / 20, col = rr - r * 20;
        int gy = y - 2 + r, gx = p0c - 2 + col;
        bool v = ((unsigned)gy < HH && (unsigned)gx < WW);
        int c_lo = ((pr >> 2) << 3) + (pr & 3);
        const float* src = xb + c_lo * HWp + gy * WW + gx;
        float a  = v ? src[0]       : 0.f;
        float bb = v ? src[4 * HWp] : 0.f;
        int cw = ((pr >> 2) << 3) + ((pr & 3) << 1);
        *(float2*)(ts + rr * TP + cw) = make_float2(a, bb);
    }

    // ---- setup table: 144 (tap, px) items ----
    for (int i = tid; i < 144; i += 128) {
        int tap = i >> 4, px = i & 15;
        int p = p0c + px;
        int yx = y * WW + p;
        float ofy = omb[(2 * tap) * HWp + yx];
        float ofx = omb[(2 * tap + 1) * HWp + yx];
        float m   = omb[(18 + tap) * HWp + yx];
        float py  = ofy + (float)y + (float)(tap / 3) - 1.f;
        float pxx = ofx + (float)p + (float)(tap % 3) - 1.f;
        float fy = floorf(py), fx = floorf(pxx);
        int   y0 = (int)fy,    x0 = (int)fx;
        float wy1 = py - fy,  wx1 = pxx - fx;
        float wy0 = 1.f - wy1, wx0 = 1.f - wx1;
        bool vy0 = ((unsigned)y0 < HH),  vy1 = ((unsigned)(y0 + 1) < HH);
        bool vx0 = ((unsigned)x0 < WW),  vx1 = ((unsigned)(x0 + 1) < WW);
        float4 wv;
        wv.x = (vy0 && vx0) ? wy0 * wx0 * m : 0.f;
        wv.y = (vy0 && vx1) ? wy0 * wx1 * m : 0.f;
        wv.z = (vy1 && vx0) ? wy1 * wx0 * m : 0.f;
        wv.w = (vy1 && vx1) ? wy1 * wx1 * m : 0.f;
        sw[tap][px] = wv;
        int ry = y0 - y + 2;
        int rx = x0 - p0c + 2;
        sp[tap][px] = (ry * 20 + rx) * TP;
        if (!(((unsigned)ry <= 3u) && ((unsigned)rx <= 18u))) allin[tap] = 0;
    }
    __syncthreads();

    float acc[8][4];
#pragma unroll
    for (int n = 0; n < 8; n++)
#pragma unroll
        for (int j = 0; j < 4; j++) acc[n][j] = 0.f;

    for (int tap = 0; tap < 9; tap++) {
        if (allin[tap]) {
            // ---- fast path: table + LDS.64 paired-channel gather ----
            float4 wA = sw[tap][lane >> 2];
            float4 wB = sw[tap][8 + (lane >> 2)];
            int baseA = sp[tap][lane >> 2];
            int baseB = sp[tap][8 + (lane >> 2)];
#pragma unroll
            for (int kq = 0; kq < 2; kq++) {
                int ks = kh * 2 + kq;
                int cw = (ks << 3) + ((lane & 3) << 1);
                const float2* tA = (const float2*)(ts + baseA + cw);
                const float2* tB = (const float2*)(ts + baseB + cw);
                float2 A0 = tA[0], A1 = tA[TP/2], A2 = tA[10*TP], A3 = tA[10*TP + TP/2];
                float2 B0 = tB[0], B1 = tB[TP/2], B2 = tB[10*TP], B3 = tB[10*TP + TP/2];

                float va0 = wA.x*A0.x + wA.y*A1.x + wA.z*A2.x + wA.w*A3.x;
                float va1 = wB.x*B0.x + wB.y*B1.x + wB.z*B2.x + wB.w*B3.x;
                float va2 = wA.x*A0.y + wA.y*A1.y + wA.z*A2.y + wA.w*A3.y;
                float va3 = wB.x*B0.y + wB.y*B1.y + wB.z*B2.y + wB.w*B3.y;

                uint32_t h0 = __float_as_uint(va0);
                uint32_t h1 = __float_as_uint(va1);
                uint32_t h2 = __float_as_uint(va2);
                uint32_t h3 = __float_as_uint(va3);

                const float4* bq = g_wB4 + ((tap * 8 + ks) * 4) * 32 + lane;
#pragma unroll
                for (int ntp = 0; ntp < 4; ntp++) {
                    float4 bv = __ldg(bq + ntp * 32);
                    mma_t(acc[ntp * 2],     h0, h1, h2, h3,
                          __float_as_uint(bv.x), __float_as_uint(bv.y));
                    mma_t(acc[ntp * 2 + 1], h0, h1, h2, h3,
                          __float_as_uint(bv.z), __float_as_uint(bv.w));
                }
            }
        } else {
            // ---- fallback: exact global gather (rare) ----
            float wA[4], wB[4];
            int   oA[4], oB[4];
#pragma unroll
            for (int s = 0; s < 2; s++) {
                int yx = s ? yx1 : yx0;
                int px = s ? p1 : p0;
                float ofy = omb[(2 * tap) * HWp + yx];
                float ofx = omb[(2 * tap + 1) * HWp + yx];
                float m   = omb[(18 + tap) * HWp + yx];
                float py = ofy + (float)y  + (float)(tap / 3) - 1.f;
                float pxx = ofx + (float)px + (float)(tap % 3) - 1.f;
                float fy = floorf(py), fx = floorf(pxx);
                int   y0 = (int)fy,    x0 = (int)fx;
                float wy1 = py - fy,  wx1 = pxx - fx;
                float wy0 = 1.f - wy1, wx0 = 1.f - wx1;
                bool vy0 = ((unsigned)y0 < HH),      vy1 = ((unsigned)(y0 + 1) < HH);
                bool vx0 = ((unsigned)x0 < WW),      vx1 = ((unsigned)(x0 + 1) < WW);
                int cy0 = min(max(y0, 0), HH - 1),   cy1 = min(max(y0 + 1, 0), HH - 1);
                int cx0 = min(max(x0, 0), WW - 1),   cx1 = min(max(x0 + 1, 0), WW - 1);
                float* wp = s ? wB : wA;
                int*   op = s ? oB : oA;
                wp[0] = (vy0 && vx0) ? wy0 * wx0 * m : 0.f;
                wp[1] = (vy0 && vx1) ? wy0 * wx1 * m : 0.f;
                wp[2] = (vy1 && vx0) ? wy1 * wx0 * m : 0.f;
                wp[3] = (vy1 && vx1) ? wy1 * wx1 * m : 0.f;
                op[0] = cy0 * WW + cx0; op[1] = cy0 * WW + cx1;
                op[2] = cy1 * WW + cx0; op[3] = cy1 * WW + cx1;
            }
#pragma unroll
            for (int kq = 0; kq < 2; kq++) {
                int ks = kh * 2 + kq;
                int c0 = ks * 8 + (lane & 3);
                const float* pc0 = xb + c0 * HWp;
                const float* pc1 = pc0 + 4 * HWp;

                float va0 = wA[0]*pc0[oA[0]] + wA[1]*pc0[oA[1]] + wA[2]*pc0[oA[2]] + wA[3]*pc0[oA[3]];
                float va1 = wB[0]*pc0[oB[0]] + wB[1]*pc0[oB[1]] + wB[2]*pc0[oB[2]] + wB[3]*pc0[oB[3]];
                float va2 = wA[0]*pc1[oA[0]] + wA[1]*pc1[oA[1]] + wA[2]*pc1[oA[2]] + wA[3]*pc1[oA[3]];
                float va3 = wB[0]*pc1[oB[0]] + wB[1]*pc1[oB[1]] + wB[2]*pc1[oB[2]] + wB[3]*pc1[oB[3]];

                uint32_t h0 = __float_as_uint(va0);
                uint32_t h1 = __float_as_uint(va1);
                uint32_t h2 = __float_as_uint(va2);
                uint32_t h3 = __float_as_uint(va3);

                const float4* bq = g_wB4 + ((tap * 8 + ks) * 4) * 32 + lane;
#pragma unroll
                for (int ntp = 0; ntp < 4; ntp++) {
                    float4 bv = __ldg(bq + ntp * 32);
                    mma_t(acc[ntp * 2],     h0, h1, h2, h3,
                          __float_as_uint(bv.x), __float_as_uint(bv.y));
                    mma_t(acc[ntp * 2 + 1], h0, h1, h2, h3,
                          __float_as_uint(bv.z), __float_as_uint(bv.w));
                }
            }
        }
    }

    // ---- cross-warp K reduction (reuse tile smem) ----
    __syncthreads();
    float* red = ts;
    if (kh != 0) {
#pragma unroll
        for (int n = 0; n < 8; n++)
#pragma unroll
            for (int j = 0; j < 4; j++)
                red[(kh - 1) * 1024 + (n * 4 + j) * 32 + lane] = acc[n][j];
    }
    __syncthreads();
    if (kh == 0) {
        float* tb = g_tmp + b * Cout * HWp + y * WW;
#pragma unroll
        for (int nt = 0; nt < 8; nt++) {
            int o = nt * 8 + (lane & 3) * 2;
            float r0 = acc[nt][0], r1 = acc[nt][1], r2 = acc[nt][2], r3 = acc[nt][3];
#pragma unroll
            for (int w = 0; w < 3; w++) {
                r0 += red[w * 1024 + (nt * 4 + 0) * 32 + lane];
                r1 += red[w * 1024 + (nt * 4 + 1) * 32 + lane];
                r2 += red[w * 1024 + (nt * 4 + 2) * 32 + lane];
                r3 += red[w * 1024 + (nt * 4 + 3) * 32 + lane];
            }
            tb[o * HWp + p0]       = r0;
            tb[(o + 1) * HWp + p0] = r1;
            tb[o * HWp + p1]       = r2;
            tb[(o + 1) * HWp + p1] = r3;
        }
    }
}

// ---------------------------------------------------------------------------
// kC1: partial per-channel sums (512 blocks) — exact R11 version.
// ---------------------------------------------------------------------------
__global__ __launch_bounds__(256) void kC1()
{
    __shared__ float ss[8], sq[8];
    int blk = blockIdx.x, tid = threadIdx.x;
    int c = blk >> 3, slab = blk & 7;
    float s = 0.f, q = 0.f;
#pragma unroll
    for (int b = 0; b < Bsz; b++) {
        const float4* t = (const float4*)(g_tmp + (b * Cout + c) * HWp + slab * 2048);
#pragma unroll
        for (int i = 0; i < 2; i++) {
            float4 v = t[tid + i * 256];
            s += v.x + v.y + v.z + v.w;
            q += v.x * v.x + v.y * v.y + v.z * v.z + v.w * v.w;
        }
    }
#pragma unroll
    for (int o = 16; o > 0; o >>= 1) {
        s += __shfl_down_sync(0xffffffff, s, o);
        q += __shfl_down_sync(0xffffffff, q, o);
    }
    if ((tid & 31) == 0) { ss[tid >> 5] = s; sq[tid >> 5] = q; }
    __syncthreads();
    if (tid == 0) {
        float st = 0.f, qt = 0.f;
#pragma unroll
        for (int w = 0; w < 8; w++) { st += ss[w]; qt += sq[w]; }
        g_part[blk * 2] = st;
        g_part[blk * 2 + 1] = qt;
    }
}

// ---------------------------------------------------------------------------
// kD: BN affine + ReLU; per-block bn reconstruction — exact R11 version.
// ---------------------------------------------------------------------------
__global__ __launch_bounds__(256) void kD(const float* __restrict__ gamma,
                                          const float* __restrict__ beta,
                                          float* __restrict__ out)
{
    __shared__ float sbn[2];
    int c = (blockIdx.x >> 4) & 63;
    if (threadIdx.x == 0) {
        float s = 0.f, q = 0.f;
#pragma unroll
        for (int k = 0; k < 8; k++) {
            s += g_part[(c * 8 + k) * 2];
            q += g_part[(c * 8 + k) * 2 + 1];
        }
        float n = (float)(Bsz * HWp);
        float mean = s / n;
        float var  = q / n - mean * mean;
        float sc = gamma[c] * rsqrtf(var + 1e-5f);
        sbn[0] = sc;
        sbn[1] = beta[c] - mean * sc;
    }
    __syncthreads();
    float sc = sbn[0], sh = sbn[1];

    int i = blockIdx.x * 256 + threadIdx.x;
    float4 v = ((const float4*)g_tmp)[i];
    float4 r;
    r.x = fmaxf(v.x * sc + sh, 0.f);
    r.y = fmaxf(v.y * sc + sh, 0.f);
    r.z = fmaxf(v.z * sc + sh, 0.f);
    r.w = fmaxf(v.w * sc + sh, 0.f);
    ((float4*)out)[i] = r;
}

// ---------------------------------------------------------------------------
extern "C" void kernel_launch(void* const* d_in, const int* in_sizes, int n_in,
                              void* d_out, int out_size)
{
    const float* x      = (const float*)d_in[0];
    const float* conv_w = (const float*)d_in[1];
    const float* off_w  = (const float*)d_in[2];
    const float* off_b  = (const float*)d_in[3];
    const float* mask_w = (const float*)d_in[4];
    const float* mask_b = (const float*)d_in[5];
    const float* gamma  = (const float*)d_in[6];
    const float* beta   = (const float*)d_in[7];
    float* out = (float*)d_out;

    kW<<<54, 256>>>(conv_w, off_w, mask_w);
    kA6<<<2048, 128>>>(x, off_b, mask_b);
    kB15<<<2048, 128>>>(x);
    kC1<<<512, 256>>>();
    kD<<<(Bsz * Cout * HWp / 4) / 256, 256>>>(gamma, beta, out);
}

// round 16
// speedup vs baseline: 1.0289x; 1.0289x over previous
#include <cuda_runtime.h>
#include <cstdint>
#include <math.h>

#define HH 128
#define WW 128
#define HWp 16384
#define Cin 64
#define Cout 64
#define Bsz 2
#define NPIX 32768

// ---------------------------------------------------------------------------
// Scratch (no allocations allowed)
// ---------------------------------------------------------------------------
__device__ float  g_om[Bsz*27*HWp];     // 18 raw offsets + 9 sigmoided masks
__device__ float4 g_wB4[9*8*4*32];      // kB B-frags nt-pair packed
__device__ float4 g_wA4[9*8*2*32];      // kA B-frags nt-pair packed
__device__ float  g_tmp[Bsz*Cout*HWp];  // pre-BN conv output (NCHW)
__device__ float  g_part[512*2];        // kC partial sums [c*8+slab][{s,q}]

// ---------------------------------------------------------------------------
__device__ __forceinline__ uint32_t cvt_tf32(float v) {
    uint32_t r;
    asm("cvt.rna.tf32.f32 %0, %1;" : "=r"(r) : "f"(v));
    return r;
}
__device__ __forceinline__ void mma_t(float* d,
    uint32_t a0, uint32_t a1, uint32_t a2, uint32_t a3,
    uint32_t b0, uint32_t b1)
{
    asm volatile("mma.sync.aligned.m16n8k8.row.col.f32.tf32.tf32.f32 "
        "{%0,%1,%2,%3}, {%4,%5,%6,%7}, {%8,%9}, {%0,%1,%2,%3};"
        : "+f"(d[0]), "+f"(d[1]), "+f"(d[2]), "+f"(d[3])
        : "r"(a0), "r"(a1), "r"(a2), "r"(a3), "r"(b0), "r"(b1));
}

// ---------------------------------------------------------------------------
// kW: pack both weight sets (merged kWB + kWA).
// ---------------------------------------------------------------------------
__global__ void kW(const float* __restrict__ w,
                   const float* __restrict__ off_w, const float* __restrict__ mask_w)
{
    if (blockIdx.x < 36) {
        int i = blockIdx.x * 256 + threadIdx.x;        // 9*8*4*32 = 9216
        if (i >= 9*8*4*32) return;
        int lane = i & 31;
        int ntp  = (i >> 5) & 3;
        int ks   = (i >> 7) & 7;
        int tap  = i >> 10;
        int o0 = (ntp * 2) * 8 + (lane >> 2);
        int o1 = o0 + 8;
        int c0 = ks * 8 + (lane & 3);
        float4 r;
        r.x = __uint_as_float(cvt_tf32(w[o0 * 576 + c0 * 9 + tap]));
        r.y = __uint_as_float(cvt_tf32(w[o0 * 576 + (c0 + 4) * 9 + tap]));
        r.z = __uint_as_float(cvt_tf32(w[o1 * 576 + c0 * 9 + tap]));
        r.w = __uint_as_float(cvt_tf32(w[o1 * 576 + (c0 + 4) * 9 + tap]));
        g_wB4[i] = r;
    } else {
        int i = (blockIdx.x - 36) * 256 + threadIdx.x; // 9*8*2*32 = 4608
        if (i >= 9*8*2*32) return;
        int lane = i & 31;
        int ntp  = (i >> 5) & 1;
        int ks   = (i >> 6) & 7;
        int tap  = i >> 9;
        int c0 = ks * 8 + (lane & 3);
        float v[4];
#pragma unroll
        for (int h = 0; h < 2; h++) {
            int o = (ntp * 2 + h) * 8 + (lane >> 2);
            float a = 0.f, bb = 0.f;
            if (o < 18) {
                a  = off_w[o * 576 + c0 * 9 + tap];
                bb = off_w[o * 576 + (c0 + 4) * 9 + tap];
            } else if (o < 27) {
                a  = mask_w[(o - 18) * 576 + c0 * 9 + tap];
                bb = mask_w[(o - 18) * 576 + (c0 + 4) * 9 + tap];
            }
            v[h * 2]     = __uint_as_float(cvt_tf32(a));
            v[h * 2 + 1] = __uint_as_float(cvt_tf32(bb));
        }
        g_wA4[i] = make_float4(v[0], v[1], v[2], v[3]);
    }
}

// ---------------------------------------------------------------------------
// kA6: offset/mask conv, smem-tiled, K-split x4, channel-pair fill. (R11)
// ---------------------------------------------------------------------------
#define TPA 72

__global__ __launch_bounds__(128, 8) void kA6(
    const float* __restrict__ x,
    const float* __restrict__ off_b, const float* __restrict__ mask_b)
{
    __shared__ float ts[54 * TPA];

    int tid = threadIdx.x, kh = tid >> 5, lane = tid & 31;
    int sidx = blockIdx.x;
    int b = sidx >> 10;
    int y = (sidx >> 3) & 127;
    int p0c = (sidx & 7) * 16;
    int p0 = p0c + (lane >> 2);
    int p1 = p0 + 8;
    const float* xb = x + b * Cin * HWp;

    for (int i = tid; i < 32 * 54; i += 128) {
        int pr = i / 54;
        int rr = i - pr * 54;
        int r = rr / 18, col = rr - r * 18;
        int gy = y - 1 + r, gx = p0c - 1 + col;
        bool v = ((unsigned)gy < HH && (unsigned)gx < WW);
        int c_lo = ((pr >> 2) << 3) + (pr & 3);
        const float* src = xb + c_lo * HWp + gy * WW + gx;
        float a  = v ? src[0]       : 0.f;
        float bb = v ? src[4 * HWp] : 0.f;
        int cw = ((pr >> 2) << 3) + ((pr & 3) << 1);
        *(float2*)(ts + rr * TPA + cw) = make_float2(a, bb);
    }
    __syncthreads();

    float acc[4][4];
#pragma unroll
    for (int n = 0; n < 4; n++)
#pragma unroll
        for (int j = 0; j < 4; j++) acc[n][j] = 0.f;

    int cwb = (kh << 4) + ((lane & 3) << 1);

#pragma unroll
    for (int tap = 0; tap < 9; tap++) {
        int posA = (tap / 3) * 18 + (tap % 3) + (lane >> 2);
        int posB = posA + 8;
#pragma unroll
        for (int kq = 0; kq < 2; kq++) {
            int cw = cwb + (kq << 3);
            float2 A  = *(const float2*)(ts + posA * TPA + cw);
            float2 Bv = *(const float2*)(ts + posB * TPA + cw);
            uint32_t a0 = cvt_tf32(A.x);
            uint32_t a1 = cvt_tf32(Bv.x);
            uint32_t a2 = cvt_tf32(A.y);
            uint32_t a3 = cvt_tf32(Bv.y);
            const float4* bq = g_wA4 + ((tap * 8 + kh * 2 + kq) * 2) * 32 + lane;
#pragma unroll
            for (int ntp = 0; ntp < 2; ntp++) {
                float4 bv = __ldg(bq + ntp * 32);
                mma_t(acc[ntp * 2],     a0, a1, a2, a3,
                      __float_as_uint(bv.x), __float_as_uint(bv.y));
                mma_t(acc[ntp * 2 + 1], a0, a1, a2, a3,
                      __float_as_uint(bv.z), __float_as_uint(bv.w));
            }
        }
    }

    __syncthreads();
    float* red = ts;
    if (kh != 0) {
#pragma unroll
        for (int n = 0; n < 4; n++)
#pragma unroll
            for (int j = 0; j < 4; j++)
                red[(kh - 1) * 512 + (n * 4 + j) * 32 + lane] = acc[n][j];
    }
    __syncthreads();
    if (kh == 0) {
        float* omb = g_om + b * 27 * HWp;
        int yx0 = y * WW + p0, yx1 = y * WW + p1;
#pragma unroll
        for (int nt = 0; nt < 4; nt++) {
            int o = nt * 8 + (lane & 3) * 2;
#pragma unroll
            for (int j = 0; j < 2; j++) {
                int oc = o + j;
                if (oc < 27) {
                    float bias = (oc < 18) ? off_b[oc] : mask_b[oc - 18];
                    float r0 = acc[nt][j]     + bias;
                    float r1 = acc[nt][j + 2] + bias;
#pragma unroll
                    for (int w = 0; w < 3; w++) {
                        r0 += red[w * 512 + (nt * 4 + j) * 32 + lane];
                        r1 += red[w * 512 + (nt * 4 + j + 2) * 32 + lane];
                    }
                    if (oc >= 18) {
                        r0 = 1.f / (1.f + expf(-r0));
                        r1 = 1.f / (1.f + expf(-r1));
                    }
                    omb[oc * HWp + yx0] = r0;
                    omb[oc * HWp + yx1] = r1;
                }
            }
        }
    }
}

// ---------------------------------------------------------------------------
// kB11: R11 mainloop (rolled taps, K-split x4, single-TF32, LDS.64 gather,
// channel-pair STS.64 fill). Verified optimum — exact R11 code.
// ---------------------------------------------------------------------------
#define TP 72

__global__ __launch_bounds__(128, 7) void kB11(const float* __restrict__ x)
{
    __shared__ float  ts[100 * TP];     // tile; reused as reduction buffer
    __shared__ float4 sw[9][16];
    __shared__ int    sp[9][16];
    __shared__ int    allin[9];

    int tid = threadIdx.x, kh = tid >> 5, lane = tid & 31;
    int sidx = blockIdx.x;
    int b = sidx >> 10;
    int y = (sidx >> 3) & 127;
    int p0c = (sidx & 7) * 16;
    int p0 = p0c + (lane >> 2);
    int p1 = p0 + 8;
    const float* xb  = x + b * Cin * HWp;
    const float* omb = g_om + b * 27 * HWp;
    int yx0 = y * WW + p0, yx1 = y * WW + p1;

    if (tid < 9) allin[tid] = 1;
    __syncthreads();

    // ---- fill tile: rows y-2..y+2, cols p0c-2..p0c+17, channel-pair STS.64 ----
    for (int i = tid; i < 32 * 100; i += 128) {
        int pr = i / 100;
        int rr = i - pr * 100;
        int r = rr / 20, col = rr - r * 20;
        int gy = y - 2 + r, gx = p0c - 2 + col;
        bool v = ((unsigned)gy < HH && (unsigned)gx < WW);
        int c_lo = ((pr >> 2) << 3) + (pr & 3);
        const float* src = xb + c_lo * HWp + gy * WW + gx;
        float a  = v ? src[0]       : 0.f;
        float bb = v ? src[4 * HWp] : 0.f;
        int cw = ((pr >> 2) << 3) + ((pr & 3) << 1);
        *(float2*)(ts + rr * TP + cw) = make_float2(a, bb);
    }

    // ---- setup table: 144 (tap, px) items ----
    for (int i = tid; i < 144; i += 128) {
        int tap = i >> 4, px = i & 15;
        int p = p0c + px;
        int yx = y * WW + p;
        float ofy = omb[(2 * tap) * HWp + yx];
        float ofx = omb[(2 * tap + 1) * HWp + yx];
        float m   = omb[(18 + tap) * HWp + yx];
        float py  = ofy + (float)y + (float)(tap / 3) - 1.f;
        float pxx = ofx + (float)p + (float)(tap % 3) - 1.f;
        float fy = floorf(py), fx = floorf(pxx);
        int   y0 = (int)fy,    x0 = (int)fx;
        float wy1 = py - fy,  wx1 = pxx - fx;
        float wy0 = 1.f - wy1, wx0 = 1.f - wx1;
        bool vy0 = ((unsigned)y0 < HH),  vy1 = ((unsigned)(y0 + 1) < HH);
        bool vx0 = ((unsigned)x0 < WW),  vx1 = ((unsigned)(x0 + 1) < WW);
        float4 wv;
        wv.x = (vy0 && vx0) ? wy0 * wx0 * m : 0.f;
        wv.y = (vy0 && vx1) ? wy0 * wx1 * m : 0.f;
        wv.z = (vy1 && vx0) ? wy1 * wx0 * m : 0.f;
        wv.w = (vy1 && vx1) ? wy1 * wx1 * m : 0.f;
        sw[tap][px] = wv;
        int ry = y0 - y + 2;
        int rx = x0 - p0c + 2;
        sp[tap][px] = (ry * 20 + rx) * TP;
        if (!(((unsigned)ry <= 3u) && ((unsigned)rx <= 18u))) allin[tap] = 0;
    }
    __syncthreads();

    float acc[8][4];
#pragma unroll
    for (int n = 0; n < 8; n++)
#pragma unroll
        for (int j = 0; j < 4; j++) acc[n][j] = 0.f;

    for (int tap = 0; tap < 9; tap++) {
        if (allin[tap]) {
            // ---- fast path: table + LDS.64 paired-channel gather ----
            float4 wA = sw[tap][lane >> 2];
            float4 wB = sw[tap][8 + (lane >> 2)];
            int baseA = sp[tap][lane >> 2];
            int baseB = sp[tap][8 + (lane >> 2)];
#pragma unroll
            for (int kq = 0; kq < 2; kq++) {
                int ks = kh * 2 + kq;
                int cw = (ks << 3) + ((lane & 3) << 1);
                const float2* tA = (const float2*)(ts + baseA + cw);
                const float2* tB = (const float2*)(ts + baseB + cw);
                float2 A0 = tA[0], A1 = tA[TP/2], A2 = tA[10*TP], A3 = tA[10*TP + TP/2];
                float2 B0 = tB[0], B1 = tB[TP/2], B2 = tB[10*TP], B3 = tB[10*TP + TP/2];

                float va0 = wA.x*A0.x + wA.y*A1.x + wA.z*A2.x + wA.w*A3.x;
                float va1 = wB.x*B0.x + wB.y*B1.x + wB.z*B2.x + wB.w*B3.x;
                float va2 = wA.x*A0.y + wA.y*A1.y + wA.z*A2.y + wA.w*A3.y;
                float va3 = wB.x*B0.y + wB.y*B1.y + wB.z*B2.y + wB.w*B3.y;

                uint32_t h0 = cvt_tf32(va0);
                uint32_t h1 = cvt_tf32(va1);
                uint32_t h2 = cvt_tf32(va2);
                uint32_t h3 = cvt_tf32(va3);

                const float4* bq = g_wB4 + ((tap * 8 + ks) * 4) * 32 + lane;
#pragma unroll
                for (int ntp = 0; ntp < 4; ntp++) {
                    float4 bv = __ldg(bq + ntp * 32);
                    mma_t(acc[ntp * 2],     h0, h1, h2, h3,
                          __float_as_uint(bv.x), __float_as_uint(bv.y));
                    mma_t(acc[ntp * 2 + 1], h0, h1, h2, h3,
                          __float_as_uint(bv.z), __float_as_uint(bv.w));
                }
            }
        } else {
            // ---- fallback: exact global gather (rare) ----
            float wA[4], wB[4];
            int   oA[4], oB[4];
#pragma unroll
            for (int s = 0; s < 2; s++) {
                int yx = s ? yx1 : yx0;
                int px = s ? p1 : p0;
                float ofy = omb[(2 * tap) * HWp + yx];
                float ofx = omb[(2 * tap + 1) * HWp + yx];
                float m   = omb[(18 + tap) * HWp + yx];
                float py = ofy + (float)y  + (float)(tap / 3) - 1.f;
                float pxx = ofx + (float)px + (float)(tap % 3) - 1.f;
                float fy = floorf(py), fx = floorf(pxx);
                int   y0 = (int)fy,    x0 = (int)fx;
                float wy1 = py - fy,  wx1 = pxx - fx;
                float wy0 = 1.f - wy1, wx0 = 1.f - wx1;
                bool vy0 = ((unsigned)y0 < HH),      vy1 = ((unsigned)(y0 + 1) < HH);
                bool vx0 = ((unsigned)x0 < WW),      vx1 = ((unsigned)(x0 + 1) < WW);
                int cy0 = min(max(y0, 0), HH - 1),   cy1 = min(max(y0 + 1, 0), HH - 1);
                int cx0 = min(max(x0, 0), WW - 1),   cx1 = min(max(x0 + 1, 0), WW - 1);
                float* wp = s ? wB : wA;
                int*   op = s ? oB : oA;
                wp[0] = (vy0 && vx0) ? wy0 * wx0 * m : 0.f;
                wp[1] = (vy0 && vx1) ? wy0 * wx1 * m : 0.f;
                wp[2] = (vy1 && vx0) ? wy1 * wx0 * m : 0.f;
                wp[3] = (vy1 && vx1) ? wy1 * wx1 * m : 0.f;
                op[0] = cy0 * WW + cx0; op[1] = cy0 * WW + cx1;
                op[2] = cy1 * WW + cx0; op[3] = cy1 * WW + cx1;
            }
#pragma unroll
            for (int kq = 0; kq < 2; kq++) {
                int ks = kh * 2 + kq;
                int c0 = ks * 8 + (lane & 3);
                const float* pc0 = xb + c0 * HWp;
                const float* pc1 = pc0 + 4 * HWp;

                float va0 = wA[0]*pc0[oA[0]] + wA[1]*pc0[oA[1]] + wA[2]*pc0[oA[2]] + wA[3]*pc0[oA[3]];
                float va1 = wB[0]*pc0[oB[0]] + wB[1]*pc0[oB[1]] + wB[2]*pc0[oB[2]] + wB[3]*pc0[oB[3]];
                float va2 = wA[0]*pc1[oA[0]] + wA[1]*pc1[oA[1]] + wA[2]*pc1[oA[2]] + wA[3]*pc1[oA[3]];
                float va3 = wB[0]*pc1[oB[0]] + wB[1]*pc1[oB[1]] + wB[2]*pc1[oB[2]] + wB[3]*pc1[oB[3]];

                uint32_t h0 = cvt_tf32(va0);
                uint32_t h1 = cvt_tf32(va1);
                uint32_t h2 = cvt_tf32(va2);
                uint32_t h3 = cvt_tf32(va3);

                const float4* bq = g_wB4 + ((tap * 8 + ks) * 4) * 32 + lane;
#pragma unroll
                for (int ntp = 0; ntp < 4; ntp++) {
                    float4 bv = __ldg(bq + ntp * 32);
                    mma_t(acc[ntp * 2],     h0, h1, h2, h3,
                          __float_as_uint(bv.x), __float_as_uint(bv.y));
                    mma_t(acc[ntp * 2 + 1], h0, h1, h2, h3,
                          __float_as_uint(bv.z), __float_as_uint(bv.w));
                }
            }
        }
    }

    // ---- cross-warp K reduction (reuse tile smem) ----
    __syncthreads();
    float* red = ts;
    if (kh != 0) {
#pragma unroll
        for (int n = 0; n < 8; n++)
#pragma unroll
            for (int j = 0; j < 4; j++)
                red[(kh - 1) * 1024 + (n * 4 + j) * 32 + lane] = acc[n][j];
    }
    __syncthreads();
    if (kh == 0) {
        float* tb = g_tmp + b * Cout * HWp + y * WW;
#pragma unroll
        for (int nt = 0; nt < 8; nt++) {
            int o = nt * 8 + (lane & 3) * 2;
            float r0 = acc[nt][0], r1 = acc[nt][1], r2 = acc[nt][2], r3 = acc[nt][3];
#pragma unroll
            for (int w = 0; w < 3; w++) {
                r0 += red[w * 1024 + (nt * 4 + 0) * 32 + lane];
                r1 += red[w * 1024 + (nt * 4 + 1) * 32 + lane];
                r2 += red[w * 1024 + (nt * 4 + 2) * 32 + lane];
                r3 += red[w * 1024 + (nt * 4 + 3) * 32 + lane];
            }
            tb[o * HWp + p0]       = r0;
            tb[(o + 1) * HWp + p0] = r1;
            tb[o * HWp + p1]       = r2;
            tb[(o + 1) * HWp + p1] = r3;
        }
    }
}

// ---------------------------------------------------------------------------
// kC1: partial per-channel sums (512 blocks) — exact R11 version.
// ---------------------------------------------------------------------------
__global__ __launch_bounds__(256) void kC1()
{
    __shared__ float ss[8], sq[8];
    int blk = blockIdx.x, tid = threadIdx.x;
    int c = blk >> 3, slab = blk & 7;
    float s = 0.f, q = 0.f;
#pragma unroll
    for (int b = 0; b < Bsz; b++) {
        const float4* t = (const float4*)(g_tmp + (b * Cout + c) * HWp + slab * 2048);
#pragma unroll
        for (int i = 0; i < 2; i++) {
            float4 v = t[tid + i * 256];
            s += v.x + v.y + v.z + v.w;
            q += v.x * v.x + v.y * v.y + v.z * v.z + v.w * v.w;
        }
    }
#pragma unroll
    for (int o = 16; o > 0; o >>= 1) {
        s += __shfl_down_sync(0xffffffff, s, o);
        q += __shfl_down_sync(0xffffffff, q, o);
    }
    if ((tid & 31) == 0) { ss[tid >> 5] = s; sq[tid >> 5] = q; }
    __syncthreads();
    if (tid == 0) {
        float st = 0.f, qt = 0.f;
#pragma unroll
        for (int w = 0; w < 8; w++) { st += ss[w]; qt += sq[w]; }
        g_part[blk * 2] = st;
        g_part[blk * 2 + 1] = qt;
    }
}

// ---------------------------------------------------------------------------
// kD: BN affine + ReLU; per-block bn reconstruction — exact R11 version.
// ---------------------------------------------------------------------------
__global__ __launch_bounds__(256) void kD(const float* __restrict__ gamma,
                                          const float* __restrict__ beta,
                                          float* __restrict__ out)
{
    __shared__ float sbn[2];
    int c = (blockIdx.x >> 4) & 63;
    if (threadIdx.x == 0) {
        float s = 0.f, q = 0.f;
#pragma unroll
        for (int k = 0; k < 8; k++) {
            s += g_part[(c * 8 + k) * 2];
            q += g_part[(c * 8 + k) * 2 + 1];
        }
        float n = (float)(Bsz * HWp);
        float mean = s / n;
        float var  = q / n - mean * mean;
        float sc = gamma[c] * rsqrtf(var + 1e-5f);
        sbn[0] = sc;
        sbn[1] = beta[c] - mean * sc;
    }
    __syncthreads();
    float sc = sbn[0], sh = sbn[1];

    int i = blockIdx.x * 256 + threadIdx.x;
    float4 v = ((const float4*)g_tmp)[i];
    float4 r;
    r.x = fmaxf(v.x * sc + sh, 0.f);
    r.y = fmaxf(v.y * sc + sh, 0.f);
    r.z = fmaxf(v.z * sc + sh, 0.f);
    r.w = fmaxf(v.w * sc + sh, 0.f);
    ((float4*)out)[i] = r;
}

// ---------------------------------------------------------------------------
extern "C" void kernel_launch(void* const* d_in, const int* in_sizes, int n_in,
                              void* d_out, int out_size)
{
    const float* x      = (const float*)d_in[0];
    const float* conv_w = (const float*)d_in[1];
    const float* off_w  = (const float*)d_in[2];
    const float* off_b  = (const float*)d_in[3];
    const float* mask_w = (const float*)d_in[4];
    const float* mask_b = (const float*)d_in[5];
    const float* gamma  = (const float*)d_in[6];
    const float* beta   = (const float*)d_in[7];
    float* out = (float*)d_out;

    kW<<<54, 256>>>(conv_w, off_w, mask_w);
    kA6<<<2048, 128>>>(x, off_b, mask_b);
    kB11<<<2048, 128>>>(x);
    kC1<<<512, 256>>>();
    kD<<<(Bsz * Cout * HWp / 4) / 256, 256>>>(gamma, beta, out);
}

// round 17
// speedup vs baseline: 1.1777x; 1.1446x over previous
#include <cuda_runtime.h>
#include <cstdint>
#include <math.h>

#define HH 128
#define WW 128
#define HWp 16384
#define Cin 64
#define Cout 64
#define Bsz 2
#define NPIX 32768

// ---------------------------------------------------------------------------
// Scratch (no allocations allowed)
// ---------------------------------------------------------------------------
__device__ float4 g_wB4[9*8*4*32];      // kB B-frags nt-pair packed
__device__ float4 g_wA4[9*8*2*32];      // kA B-frags nt-pair packed
__device__ float  g_tmp[Bsz*Cout*HWp];  // pre-BN conv output (NCHW)
__device__ float  g_part[512*2];        // kC partial sums [c*8+slab][{s,q}]

// ---------------------------------------------------------------------------
__device__ __forceinline__ uint32_t cvt_tf32(float v) {
    uint32_t r;
    asm("cvt.rna.tf32.f32 %0, %1;" : "=r"(r) : "f"(v));
    return r;
}
__device__ __forceinline__ void mma_t(float* d,
    uint32_t a0, uint32_t a1, uint32_t a2, uint32_t a3,
    uint32_t b0, uint32_t b1)
{
    asm volatile("mma.sync.aligned.m16n8k8.row.col.f32.tf32.tf32.f32 "
        "{%0,%1,%2,%3}, {%4,%5,%6,%7}, {%8,%9}, {%0,%1,%2,%3};"
        : "+f"(d[0]), "+f"(d[1]), "+f"(d[2]), "+f"(d[3])
        : "r"(a0), "r"(a1), "r"(a2), "r"(a3), "r"(b0), "r"(b1));
}

// ---------------------------------------------------------------------------
// kW: pack both weight sets (merged kWB + kWA).
// ---------------------------------------------------------------------------
__global__ void kW(const float* __restrict__ w,
                   const float* __restrict__ off_w, const float* __restrict__ mask_w)
{
    if (blockIdx.x < 36) {
        int i = blockIdx.x * 256 + threadIdx.x;        // 9*8*4*32 = 9216
        if (i >= 9*8*4*32) return;
        int lane = i & 31;
        int ntp  = (i >> 5) & 3;
        int ks   = (i >> 7) & 7;
        int tap  = i >> 10;
        int o0 = (ntp * 2) * 8 + (lane >> 2);
        int o1 = o0 + 8;
        int c0 = ks * 8 + (lane & 3);
        float4 r;
        r.x = __uint_as_float(cvt_tf32(w[o0 * 576 + c0 * 9 + tap]));
        r.y = __uint_as_float(cvt_tf32(w[o0 * 576 + (c0 + 4) * 9 + tap]));
        r.z = __uint_as_float(cvt_tf32(w[o1 * 576 + c0 * 9 + tap]));
        r.w = __uint_as_float(cvt_tf32(w[o1 * 576 + (c0 + 4) * 9 + tap]));
        g_wB4[i] = r;
    } else {
        int i = (blockIdx.x - 36) * 256 + threadIdx.x; // 9*8*2*32 = 4608
        if (i >= 9*8*2*32) return;
        int lane = i & 31;
        int ntp  = (i >> 5) & 1;
        int ks   = (i >> 6) & 7;
        int tap  = i >> 9;
        int c0 = ks * 8 + (lane & 3);
        float v[4];
#pragma unroll
        for (int h = 0; h < 2; h++) {
            int o = (ntp * 2 + h) * 8 + (lane >> 2);
            float a = 0.f, bb = 0.f;
            if (o < 18) {
                a  = off_w[o * 576 + c0 * 9 + tap];
                bb = off_w[o * 576 + (c0 + 4) * 9 + tap];
            } else if (o < 27) {
                a  = mask_w[(o - 18) * 576 + c0 * 9 + tap];
                bb = mask_w[(o - 18) * 576 + (c0 + 4) * 9 + tap];
            }
            v[h * 2]     = __uint_as_float(cvt_tf32(a));
            v[h * 2 + 1] = __uint_as_float(cvt_tf32(bb));
        }
        g_wA4[i] = make_float4(v[0], v[1], v[2], v[3]);
    }
}

// ---------------------------------------------------------------------------
// kAB: fused offset/mask conv (kA phase, reusing the kB tile) + deformable
// gather + mma tf32 GEMM (exact kB11 mainloop). som holds the 27x16
// offset/mask values in smem; setup + fallback read it via LDS.
// ---------------------------------------------------------------------------
#define TP 72

__global__ __launch_bounds__(128, 7) void kAB(
    const float* __restrict__ x,
    const float* __restrict__ off_b, const float* __restrict__ mask_b)
{
    __shared__ float ts[100 * TP];   // 28800 B tile; reused as final reduction
    __shared__ float U[1536];        // 6144 B: kA red; later sw(576f)+sp(144i)
    __shared__ float som[27 * 16];   // offset/mask results [oc][px]
    __shared__ int   allin[9];

    float4* sw4 = (float4*)U;        // sw[tap*16+px], 576 floats
    int*    spi = (int*)(U + 576);   // sp[tap*16+px], 144 ints

    int tid = threadIdx.x, kh = tid >> 5, lane = tid & 31;
    int sidx = blockIdx.x;
    int b = sidx >> 10;
    int y = (sidx >> 3) & 127;
    int p0c = (sidx & 7) * 16;
    int p0 = p0c + (lane >> 2);
    int p1 = p0 + 8;
    const float* xb = x + b * Cin * HWp;

    if (tid < 9) allin[tid] = 1;

    // ---- fill tile: rows y-2..y+2, cols p0c-2..p0c+17, channel-pair STS.64 ----
    for (int i = tid; i < 32 * 100; i += 128) {
        int pr = i / 100;
        int rr = i - pr * 100;
        int r = rr / 20, col = rr - r * 20;
        int gy = y - 2 + r, gx = p0c - 2 + col;
        bool v = ((unsigned)gy < HH && (unsigned)gx < WW);
        int c_lo = ((pr >> 2) << 3) + (pr & 3);
        const float* src = xb + c_lo * HWp + gy * WW + gx;
        float a  = v ? src[0]       : 0.f;
        float bb = v ? src[4 * HWp] : 0.f;
        int cw = ((pr >> 2) << 3) + ((pr & 3) << 1);
        *(float2*)(ts + rr * TP + cw) = make_float2(a, bb);
    }
    __syncthreads();

    int cwb = (kh << 4) + ((lane & 3) << 1);

    // ================= kA phase: offset/mask conv (K-split x4) =================
    {
        float accA[4][4];
#pragma unroll
        for (int n = 0; n < 4; n++)
#pragma unroll
            for (int j = 0; j < 4; j++) accA[n][j] = 0.f;

#pragma unroll
        for (int tap = 0; tap < 9; tap++) {
            int posA = ((tap / 3) + 1) * 20 + (tap % 3) + 1 + (lane >> 2);
            int posB = posA + 8;
#pragma unroll
            for (int kq = 0; kq < 2; kq++) {
                int cw = cwb + (kq << 3);
                float2 A  = *(const float2*)(ts + posA * TP + cw);
                float2 Bv = *(const float2*)(ts + posB * TP + cw);
                uint32_t a0 = cvt_tf32(A.x);
                uint32_t a1 = cvt_tf32(Bv.x);
                uint32_t a2 = cvt_tf32(A.y);
                uint32_t a3 = cvt_tf32(Bv.y);
                const float4* bq = g_wA4 + ((tap * 8 + kh * 2 + kq) * 2) * 32 + lane;
#pragma unroll
                for (int ntp = 0; ntp < 2; ntp++) {
                    float4 bv = __ldg(bq + ntp * 32);
                    mma_t(accA[ntp * 2],     a0, a1, a2, a3,
                          __float_as_uint(bv.x), __float_as_uint(bv.y));
                    mma_t(accA[ntp * 2 + 1], a0, a1, a2, a3,
                          __float_as_uint(bv.z), __float_as_uint(bv.w));
                }
            }
        }

        if (kh != 0) {
#pragma unroll
            for (int n = 0; n < 4; n++)
#pragma unroll
                for (int j = 0; j < 4; j++)
                    U[(kh - 1) * 512 + (n * 4 + j) * 32 + lane] = accA[n][j];
        }
        __syncthreads();
        if (kh == 0) {
#pragma unroll
            for (int nt = 0; nt < 4; nt++) {
                int o = nt * 8 + (lane & 3) * 2;
#pragma unroll
                for (int j = 0; j < 2; j++) {
                    int oc = o + j;
                    if (oc < 27) {
                        float bias = (oc < 18) ? off_b[oc] : mask_b[oc - 18];
                        float r0 = accA[nt][j]     + bias;
                        float r1 = accA[nt][j + 2] + bias;
#pragma unroll
                        for (int w = 0; w < 3; w++) {
                            r0 += U[w * 512 + (nt * 4 + j) * 32 + lane];
                            r1 += U[w * 512 + (nt * 4 + j + 2) * 32 + lane];
                        }
                        if (oc >= 18) {
                            r0 = 1.f / (1.f + expf(-r0));
                            r1 = 1.f / (1.f + expf(-r1));
                        }
                        som[oc * 16 + (lane >> 2)]     = r0;
                        som[oc * 16 + 8 + (lane >> 2)] = r1;
                    }
                }
            }
        }
    }
    __syncthreads();   // som ready; U (red) dead -> reuse for sw/sp

    // ---- setup table: 144 (tap, px) items, reading som via LDS ----
    for (int i = tid; i < 144; i += 128) {
        int tap = i >> 4, px = i & 15;
        int p = p0c + px;
        float ofy = som[(2 * tap) * 16 + px];
        float ofx = som[(2 * tap + 1) * 16 + px];
        float m   = som[(18 + tap) * 16 + px];
        float py  = ofy + (float)y + (float)(tap / 3) - 1.f;
        float pxx = ofx + (float)p + (float)(tap % 3) - 1.f;
        float fy = floorf(py), fx = floorf(pxx);
        int   y0 = (int)fy,    x0 = (int)fx;
        float wy1 = py - fy,  wx1 = pxx - fx;
        float wy0 = 1.f - wy1, wx0 = 1.f - wx1;
        bool vy0 = ((unsigned)y0 < HH),  vy1 = ((unsigned)(y0 + 1) < HH);
        bool vx0 = ((unsigned)x0 < WW),  vx1 = ((unsigned)(x0 + 1) < WW);
        float4 wv;
        wv.x = (vy0 && vx0) ? wy0 * wx0 * m : 0.f;
        wv.y = (vy0 && vx1) ? wy0 * wx1 * m : 0.f;
        wv.z = (vy1 && vx0) ? wy1 * wx0 * m : 0.f;
        wv.w = (vy1 && vx1) ? wy1 * wx1 * m : 0.f;
        sw4[tap * 16 + px] = wv;
        int ry = y0 - y + 2;
        int rx = x0 - p0c + 2;
        spi[tap * 16 + px] = (ry * 20 + rx) * TP;
        if (!(((unsigned)ry <= 3u) && ((unsigned)rx <= 18u))) allin[tap] = 0;
    }
    __syncthreads();

    // ================= kB mainloop (exact kB11 structure) =================
    float acc[8][4];
#pragma unroll
    for (int n = 0; n < 8; n++)
#pragma unroll
        for (int j = 0; j < 4; j++) acc[n][j] = 0.f;

    for (int tap = 0; tap < 9; tap++) {
        if (allin[tap]) {
            // ---- fast path: table + LDS.64 paired-channel gather ----
            float4 wA = sw4[tap * 16 + (lane >> 2)];
            float4 wB = sw4[tap * 16 + 8 + (lane >> 2)];
            int baseA = spi[tap * 16 + (lane >> 2)];
            int baseB = spi[tap * 16 + 8 + (lane >> 2)];
#pragma unroll
            for (int kq = 0; kq < 2; kq++) {
                int ks = kh * 2 + kq;
                int cw = (ks << 3) + ((lane & 3) << 1);
                const float2* tA = (const float2*)(ts + baseA + cw);
                const float2* tB = (const float2*)(ts + baseB + cw);
                float2 A0 = tA[0], A1 = tA[TP/2], A2 = tA[10*TP], A3 = tA[10*TP + TP/2];
                float2 B0 = tB[0], B1 = tB[TP/2], B2 = tB[10*TP], B3 = tB[10*TP + TP/2];

                float va0 = wA.x*A0.x + wA.y*A1.x + wA.z*A2.x + wA.w*A3.x;
                float va1 = wB.x*B0.x + wB.y*B1.x + wB.z*B2.x + wB.w*B3.x;
                float va2 = wA.x*A0.y + wA.y*A1.y + wA.z*A2.y + wA.w*A3.y;
                float va3 = wB.x*B0.y + wB.y*B1.y + wB.z*B2.y + wB.w*B3.y;

                uint32_t h0 = cvt_tf32(va0);
                uint32_t h1 = cvt_tf32(va1);
                uint32_t h2 = cvt_tf32(va2);
                uint32_t h3 = cvt_tf32(va3);

                const float4* bq = g_wB4 + ((tap * 8 + ks) * 4) * 32 + lane;
#pragma unroll
                for (int ntp = 0; ntp < 4; ntp++) {
                    float4 bv = __ldg(bq + ntp * 32);
                    mma_t(acc[ntp * 2],     h0, h1, h2, h3,
                          __float_as_uint(bv.x), __float_as_uint(bv.y));
                    mma_t(acc[ntp * 2 + 1], h0, h1, h2, h3,
                          __float_as_uint(bv.z), __float_as_uint(bv.w));
                }
            }
        } else {
            // ---- fallback: exact global gather (rare); om values from som ----
            float wA[4], wB[4];
            int   oA[4], oB[4];
#pragma unroll
            for (int s = 0; s < 2; s++) {
                int pxs = (s ? 8 : 0) + (lane >> 2);
                int px = (s ? p1 : p0);
                float ofy = som[(2 * tap) * 16 + pxs];
                float ofx = som[(2 * tap + 1) * 16 + pxs];
                float m   = som[(18 + tap) * 16 + pxs];
                float py = ofy + (float)y  + (float)(tap / 3) - 1.f;
                float pxx = ofx + (float)px + (float)(tap % 3) - 1.f;
                float fy = floorf(py), fx = floorf(pxx);
                int   y0 = (int)fy,    x0 = (int)fx;
                float wy1 = py - fy,  wx1 = pxx - fx;
                float wy0 = 1.f - wy1, wx0 = 1.f - wx1;
                bool vy0 = ((unsigned)y0 < HH),      vy1 = ((unsigned)(y0 + 1) < HH);
                bool vx0 = ((unsigned)x0 < WW),      vx1 = ((unsigned)(x0 + 1) < WW);
                int cy0 = min(max(y0, 0), HH - 1),   cy1 = min(max(y0 + 1, 0), HH - 1);
                int cx0 = min(max(x0, 0), WW - 1),   cx1 = min(max(x0 + 1, 0), WW - 1);
                float* wp = s ? wB : wA;
                int*   op = s ? oB : oA;
                wp[0] = (vy0 && vx0) ? wy0 * wx0 * m : 0.f;
                wp[1] = (vy0 && vx1) ? wy0 * wx1 * m : 0.f;
                wp[2] = (vy1 && vx0) ? wy1 * wx0 * m : 0.f;
                wp[3] = (vy1 && vx1) ? wy1 * wx1 * m : 0.f;
                op[0] = cy0 * WW + cx0; op[1] = cy0 * WW + cx1;
                op[2] = cy1 * WW + cx0; op[3] = cy1 * WW + cx1;
            }
#pragma unroll
            for (int kq = 0; kq < 2; kq++) {
                int ks = kh * 2 + kq;
                int c0 = ks * 8 + (lane & 3);
                const float* pc0 = xb + c0 * HWp;
                const float* pc1 = pc0 + 4 * HWp;

                float va0 = wA[0]*pc0[oA[0]] + wA[1]*pc0[oA[1]] + wA[2]*pc0[oA[2]] + wA[3]*pc0[oA[3]];
                float va1 = wB[0]*pc0[oB[0]] + wB[1]*pc0[oB[1]] + wB[2]*pc0[oB[2]] + wB[3]*pc0[oB[3]];
                float va2 = wA[0]*pc1[oA[0]] + wA[1]*pc1[oA[1]] + wA[2]*pc1[oA[2]] + wA[3]*pc1[oA[3]];
                float va3 = wB[0]*pc1[oB[0]] + wB[1]*pc1[oB[1]] + wB[2]*pc1[oB[2]] + wB[3]*pc1[oB[3]];

                uint32_t h0 = cvt_tf32(va0);
                uint32_t h1 = cvt_tf32(va1);
                uint32_t h2 = cvt_tf32(va2);
                uint32_t h3 = cvt_tf32(va3);

                const float4* bq = g_wB4 + ((tap * 8 + ks) * 4) * 32 + lane;
#pragma unroll
                for (int ntp = 0; ntp < 4; ntp++) {
                    float4 bv = __ldg(bq + ntp * 32);
                    mma_t(acc[ntp * 2],     h0, h1, h2, h3,
                          __float_as_uint(bv.x), __float_as_uint(bv.y));
                    mma_t(acc[ntp * 2 + 1], h0, h1, h2, h3,
                          __float_as_uint(bv.z), __float_as_uint(bv.w));
                }
            }
        }
    }

    // ---- cross-warp K reduction (reuse tile smem) ----
    __syncthreads();
    float* red = ts;
    if (kh != 0) {
#pragma unroll
        for (int n = 0; n < 8; n++)
#pragma unroll
            for (int j = 0; j < 4; j++)
                red[(kh - 1) * 1024 + (n * 4 + j) * 32 + lane] = acc[n][j];
    }
    __syncthreads();
    if (kh == 0) {
        float* tb = g_tmp + b * Cout * HWp + y * WW;
#pragma unroll
        for (int nt = 0; nt < 8; nt++) {
            int o = nt * 8 + (lane & 3) * 2;
            float r0 = acc[nt][0], r1 = acc[nt][1], r2 = acc[nt][2], r3 = acc[nt][3];
#pragma unroll
            for (int w = 0; w < 3; w++) {
                r0 += red[w * 1024 + (nt * 4 + 0) * 32 + lane];
                r1 += red[w * 1024 + (nt * 4 + 1) * 32 + lane];
                r2 += red[w * 1024 + (nt * 4 + 2) * 32 + lane];
                r3 += red[w * 1024 + (nt * 4 + 3) * 32 + lane];
            }
            tb[o * HWp + p0]       = r0;
            tb[(o + 1) * HWp + p0] = r1;
            tb[o * HWp + p1]       = r2;
            tb[(o + 1) * HWp + p1] = r3;
        }
    }
}

// ---------------------------------------------------------------------------
// kC1: partial per-channel sums (512 blocks) — exact R11 version.
// ---------------------------------------------------------------------------
__global__ __launch_bounds__(256) void kC1()
{
    __shared__ float ss[8], sq[8];
    int blk = blockIdx.x, tid = threadIdx.x;
    int c = blk >> 3, slab = blk & 7;
    float s = 0.f, q = 0.f;
#pragma unroll
    for (int b = 0; b < Bsz; b++) {
        const float4* t = (const float4*)(g_tmp + (b * Cout + c) * HWp + slab * 2048);
#pragma unroll
        for (int i = 0; i < 2; i++) {
            float4 v = t[tid + i * 256];
            s += v.x + v.y + v.z + v.w;
            q += v.x * v.x + v.y * v.y + v.z * v.z + v.w * v.w;
        }
    }
#pragma unroll
    for (int o = 16; o > 0; o >>= 1) {
        s += __shfl_down_sync(0xffffffff, s, o);
        q += __shfl_down_sync(0xffffffff, q, o);
    }
    if ((tid & 31) == 0) { ss[tid >> 5] = s; sq[tid >> 5] = q; }
    __syncthreads();
    if (tid == 0) {
        float st = 0.f, qt = 0.f;
#pragma unroll
        for (int w = 0; w < 8; w++) { st += ss[w]; qt += sq[w]; }
        g_part[blk * 2] = st;
        g_part[blk * 2 + 1] = qt;
    }
}

// ---------------------------------------------------------------------------
// kD: BN affine + ReLU; per-block bn reconstruction — exact R11 version.
// ---------------------------------------------------------------------------
__global__ __launch_bounds__(256) void kD(const float* __restrict__ gamma,
                                          const float* __restrict__ beta,
                                          float* __restrict__ out)
{
    __shared__ float sbn[2];
    int c = (blockIdx.x >> 4) & 63;
    if (threadIdx.x == 0) {
        float s = 0.f, q = 0.f;
#pragma unroll
        for (int k = 0; k < 8; k++) {
            s += g_part[(c * 8 + k) * 2];
            q += g_part[(c * 8 + k) * 2 + 1];
        }
        float n = (float)(Bsz * HWp);
        float mean = s / n;
        float var  = q / n - mean * mean;
        float sc = gamma[c] * rsqrtf(var + 1e-5f);
        sbn[0] = sc;
        sbn[1] = beta[c] - mean * sc;
    }
    __syncthreads();
    float sc = sbn[0], sh = sbn[1];

    int i = blockIdx.x * 256 + threadIdx.x;
    float4 v = ((const float4*)g_tmp)[i];
    float4 r;
    r.x = fmaxf(v.x * sc + sh, 0.f);
    r.y = fmaxf(v.y * sc + sh, 0.f);
    r.z = fmaxf(v.z * sc + sh, 0.f);
    r.w = fmaxf(v.w * sc + sh, 0.f);
    ((float4*)out)[i] = r;
}

// ---------------------------------------------------------------------------
extern "C" void kernel_launch(void* const* d_in, const int* in_sizes, int n_in,
                              void* d_out, int out_size)
{
    const float* x      = (const float*)d_in[0];
    const float* conv_w = (const float*)d_in[1];
    const float* off_w  = (const float*)d_in[2];
    const float* off_b  = (const float*)d_in[3];
    const float* mask_w = (const float*)d_in[4];
    const float* mask_b = (const float*)d_in[5];
    const float* gamma  = (const float*)d_in[6];
    const float* beta   = (const float*)d_in[7];
    float* out = (float*)d_out;

    kW<<<54, 256>>>(conv_w, off_w, mask_w);
    kAB<<<2048, 128>>>(x, off_b, mask_b);
    kC1<<<512, 256>>>();
    kD<<<(Bsz * Cout * HWp / 4) / 256, 256>>>(gamma, beta, out);
}